// round 6
// baseline (speedup 1.0000x reference)
#include <cuda_runtime.h>

// ---------------------------------------------------------------------------
// HyperConv: out[b,c,f] = sum_t x[b,c,t+1]*W[b,t,f]  (t<4095)  + bias[b,c,f]
//   W    = conv2( relu(conv1(z, ww1)+wb1), ww2 ) + wb2     (full T=4096 steps)
//   bias = conv2( relu(conv1(z, bw1)+bb1), bw2 ) + bb2     (only first 512 steps needed)
// KS=2 convs over contiguous z rows == plain GEMMs with contiguous K=2*Cin.
// ---------------------------------------------------------------------------

namespace {
constexpr int BATCH = 8;
constexpr int CCH   = 512;
constexpr int TT    = 4096;
constexpr int TZv   = 4098;
constexpr int ZDv   = 128;
constexpr int FF    = 512;
constexpr int T1W   = TT + 1;   // 4097 hidden steps for weights path
constexpr int T1B   = 513;      // hidden steps for bias path
}

// Scratch (device globals; no allocations allowed)
__device__ __align__(256) float g_h1w[BATCH * T1W * FF];   // ~67 MB
__device__ __align__(256) float g_h1b[BATCH * T1B * FF];   // ~8.4 MB
__device__ __align__(256) float g_wts[BATCH * TT  * FF];   // ~67 MB
__device__ __align__(256) float g_bias[BATCH * 512 * FF];  // ~8.4 MB

// ---------------------------------------------------------------------------
// Generic "row-pointer" GEMM:  C[m, 0:512] = A_row(m)[0:K] @ W[K,512] + biasVec
// A_row(m) = Abase + b*batchStride + t*rowStride  with m = b*rowsPerBatch + t.
// Tile: 128(M) x 64(N) x 16(K), 256 threads, 8x4 per-thread microtile.
// ---------------------------------------------------------------------------
template<bool RELU>
__global__ void __launch_bounds__(256) gemm_rows(
    const float* __restrict__ Abase, int rowsPerBatch, int rowStride, long batchStride,
    const float* __restrict__ W, int K,
    const float* __restrict__ biasVec,
    float* __restrict__ Cout, int M)
{
    __shared__ float As[16][128];   // [k][m]
    __shared__ float Bs[16][64];    // [k][n]

    const int tid = threadIdx.x;
    const int m0  = blockIdx.y * 128;
    const int n0  = blockIdx.x * 64;

    // A-load assignment: thread owns row (tid>>1), half (tid&1) -> 8 k-floats (2x float4)
    const int ar = tid >> 1;
    const int ah = tid & 1;
    const float* aptr = nullptr;
    {
        int m = m0 + ar;
        if (m < M) {
            int b = m / rowsPerBatch;
            int t = m - b * rowsPerBatch;
            aptr = Abase + (long)b * batchStride + (long)t * rowStride + ah * 8;
        }
    }
    // B-load assignment: thread owns (k = tid>>4, 4 cols at (tid&15)*4)
    const int bk = tid >> 4;
    const int bn = (tid & 15) * 4;
    const float* wptr = W + (long)bk * FF + n0 + bn;

    const int ty = tid >> 4;   // m microtile: rows ty*8 .. ty*8+7
    const int tx = tid & 15;   // n microtile: cols tx*4 .. tx*4+3

    float acc[8][4];
#pragma unroll
    for (int i = 0; i < 8; i++)
#pragma unroll
        for (int j = 0; j < 4; j++) acc[i][j] = 0.f;

    for (int kk = 0; kk < K; kk += 16) {
        float4 a0, a1;
        if (aptr) {
            a0 = *(const float4*)(aptr + kk);
            a1 = *(const float4*)(aptr + kk + 4);
        } else {
            a0 = make_float4(0.f, 0.f, 0.f, 0.f);
            a1 = a0;
        }
        const int kb = ah * 8;
        As[kb + 0][ar] = a0.x; As[kb + 1][ar] = a0.y;
        As[kb + 2][ar] = a0.z; As[kb + 3][ar] = a0.w;
        As[kb + 4][ar] = a1.x; As[kb + 5][ar] = a1.y;
        As[kb + 6][ar] = a1.z; As[kb + 7][ar] = a1.w;

        float4 bv = *(const float4*)(wptr + (long)kk * FF);
        *(float4*)&Bs[bk][bn] = bv;
        __syncthreads();

#pragma unroll
        for (int k = 0; k < 16; k++) {
            float4 av0 = *(const float4*)&As[k][ty * 8];
            float4 av1 = *(const float4*)&As[k][ty * 8 + 4];
            float4 bv2 = *(const float4*)&Bs[k][tx * 4];
            float a[8] = {av0.x, av0.y, av0.z, av0.w, av1.x, av1.y, av1.z, av1.w};
            float bb[4] = {bv2.x, bv2.y, bv2.z, bv2.w};
#pragma unroll
            for (int i = 0; i < 8; i++)
#pragma unroll
                for (int j = 0; j < 4; j++)
                    acc[i][j] = fmaf(a[i], bb[j], acc[i][j]);
        }
        __syncthreads();
    }

    float bvec[4];
#pragma unroll
    for (int j = 0; j < 4; j++) bvec[j] = biasVec[n0 + tx * 4 + j];

#pragma unroll
    for (int i = 0; i < 8; i++) {
        int m = m0 + ty * 8 + i;
        if (m < M) {
            float* cp = Cout + (long)m * FF + n0 + tx * 4;
#pragma unroll
            for (int j = 0; j < 4; j++) {
                float v = acc[i][j] + bvec[j];
                if (RELU) v = fmaxf(v, 0.f);
                cp[j] = v;
            }
        }
    }
}

// ---------------------------------------------------------------------------
// Final batched GEMM: out[b,c,f] = sum_{t<4095} x[b,c,t+1] * wts[b,t,f] + bias[b,c,f]
// Tile: 64x64x16, 256 threads, 4x4 microtile. grid = (F/64, C/64, B).
// ---------------------------------------------------------------------------
__global__ void __launch_bounds__(256) final_gemm(
    const float* __restrict__ x, const float* __restrict__ wts,
    const float* __restrict__ biasM, float* __restrict__ out)
{
    __shared__ float As[16][64];
    __shared__ float Bs[16][64];

    const int b  = blockIdx.z;
    const int m0 = blockIdx.y * 64;
    const int n0 = blockIdx.x * 64;
    const int tid = threadIdx.x;

    const float* A = x   + (long)b * CCH * TT;
    const float* W = wts + (long)b * TT * FF;

    const int ar = tid >> 2;          // row 0..63
    const int aq = (tid & 3) * 4;     // k sub-offset 0,4,8,12
    const float* aptr = A + (long)(m0 + ar) * TT + 1 + aq;   // shifted-left-by-1 x

    const int bk = tid >> 4;
    const int bn = (tid & 15) * 4;

    const int ty = tid >> 4;   // rows ty*4..+3
    const int tx = tid & 15;   // cols tx*4..+3

    float acc[4][4];
#pragma unroll
    for (int i = 0; i < 4; i++)
#pragma unroll
        for (int j = 0; j < 4; j++) acc[i][j] = 0.f;

    for (int kk = 0; kk < TT; kk += 16) {
        // scalar A loads (base is odd-offset; k=4095 is the zero pad tail)
#pragma unroll
        for (int j = 0; j < 4; j++) {
            int kglob = kk + aq + j;
            As[aq + j][ar] = (kglob < TT - 1) ? aptr[kk + j] : 0.f;
        }
        float4 bv = *(const float4*)(W + (long)(kk + bk) * FF + n0 + bn);
        *(float4*)&Bs[bk][bn] = bv;
        __syncthreads();

#pragma unroll
        for (int k = 0; k < 16; k++) {
            float4 av  = *(const float4*)&As[k][ty * 4];
            float4 bv2 = *(const float4*)&Bs[k][tx * 4];
            float a[4]  = {av.x, av.y, av.z, av.w};
            float bb[4] = {bv2.x, bv2.y, bv2.z, bv2.w};
#pragma unroll
            for (int i = 0; i < 4; i++)
#pragma unroll
                for (int j = 0; j < 4; j++)
                    acc[i][j] = fmaf(a[i], bb[j], acc[i][j]);
        }
        __syncthreads();
    }

#pragma unroll
    for (int i = 0; i < 4; i++) {
        int m = m0 + ty * 4 + i;
        long idx = ((long)b * CCH + m) * FF + n0 + tx * 4;
#pragma unroll
        for (int j = 0; j < 4; j++)
            out[idx + j] = acc[i][j] + biasM[idx + j];
    }
}

// ---------------------------------------------------------------------------
extern "C" void kernel_launch(void* const* d_in, const int* in_sizes, int n_in,
                              void* d_out, int out_size)
{
    const float* x   = (const float*)d_in[0];
    const float* z   = (const float*)d_in[1];
    const float* ww1 = (const float*)d_in[2];
    const float* wb1 = (const float*)d_in[3];
    const float* ww2 = (const float*)d_in[4];
    const float* wb2 = (const float*)d_in[5];
    const float* bw1 = (const float*)d_in[6];
    const float* bb1 = (const float*)d_in[7];
    const float* bw2 = (const float*)d_in[8];
    const float* bb2 = (const float*)d_in[9];
    float* out = (float*)d_out;

    float *h1w, *h1b, *wts, *bias;
    cudaGetSymbolAddress((void**)&h1w,  g_h1w);
    cudaGetSymbolAddress((void**)&h1b,  g_h1b);
    cudaGetSymbolAddress((void**)&wts,  g_wts);
    cudaGetSymbolAddress((void**)&bias, g_bias);

    dim3 thr(256);

    // weights path, conv1 + ReLU: M = 8*4097, K = 256
    gemm_rows<true><<<dim3(FF / 64, (BATCH * T1W + 127) / 128), thr>>>(
        z, T1W, ZDv, (long)TZv * ZDv, ww1, 2 * ZDv, wb1, h1w, BATCH * T1W);

    // bias path, conv1 + ReLU (truncated): M = 8*513, K = 256
    gemm_rows<true><<<dim3(FF / 64, (BATCH * T1B + 127) / 128), thr>>>(
        z, T1B, ZDv, (long)TZv * ZDv, bw1, 2 * ZDv, bb1, h1b, BATCH * T1B);

    // weights path, conv2: M = 8*4096, K = 1024
    gemm_rows<false><<<dim3(FF / 64, (BATCH * TT) / 128), thr>>>(
        h1w, TT, FF, (long)T1W * FF, ww2, 2 * FF, wb2, wts, BATCH * TT);

    // bias path, conv2 (truncated): M = 8*512, K = 1024
    gemm_rows<false><<<dim3(FF / 64, (BATCH * 512) / 128), thr>>>(
        h1b, 512, FF, (long)T1B * FF, bw2, 2 * FF, bb2, bias, BATCH * 512);

    // final: out = x_shift @ wts + bias   (per-batch 512x512x4095)
    final_gemm<<<dim3(FF / 64, CCH / 64, BATCH), thr>>>(x, wts, bias, out);
}

// round 11
// speedup vs baseline: 2.4320x; 2.4320x over previous
#include <cuda_runtime.h>
#include <cstdint>

// ---------------------------------------------------------------------------
// HyperConv via warp-level mma.sync tf32 (compute_103-safe: NO tcgen05).
//   out[b,c,f] = sum_{k=1..4095} x[b,c,k] * W[b,k-1,f] + bias[b,c,f]
//   W    = conv2(relu(conv1(z,ww1)+wb1), ww2)+wb2   (T=4096 steps)
//   bias = same with bw*/bb*, only first 512 steps needed
// KS=2 convs over contiguous z rows are plain GEMMs with contiguous K=2*Cin.
// All 5 GEMMs: 128x128x32 CTA tiles, 8 warps (2x4), m16n8k8 tf32 MMA,
// cp.async 3-stage pipeline, RNA-rounded tf32 inputs, fp32 accumulate.
// ---------------------------------------------------------------------------

namespace {
constexpr int BATCH = 8;
constexpr int TT    = 4096;
constexpr int TZv   = 4098;
constexpr int ZD    = 128;
constexpr int FF    = 512;
constexpr int T1W   = 4097;   // hidden steps, weights path
constexpr int T1B   = 513;    // hidden steps, bias path

constexpr int BM = 128, BN = 128, BK = 32;
constexpr int APAD = 36;                 // A smem row length (32 data + 4 pad)
constexpr int BPAD = 132;                // B smem row length (128 data + 4 pad)
constexpr int AS_F = BM * APAD;          // 4608 floats
constexpr int BS_F = BK * BPAD;          // 4224 floats
constexpr int STG_F = AS_F + BS_F;       // 8832 floats / stage
constexpr int NSTAGE = 3;
constexpr int SMEM_BYTES = NSTAGE * STG_F * 4;   // 105984 B
}

// Scratch (device globals; no allocations allowed)
__device__ __align__(256) float g_h1w[BATCH * T1W * FF];   // ~67 MB
__device__ __align__(256) float g_h1b[BATCH * T1B * FF];   // ~8.4 MB
__device__ __align__(256) float g_wts[BATCH * TT  * FF];   // ~67 MB
__device__ __align__(256) float g_bias[BATCH * 512 * FF];  // ~8.4 MB

#define DI __device__ __forceinline__

DI uint32_t smem_u32(const void* p) {
    uint32_t a;
    asm("{ .reg .u64 t; cvta.to.shared.u64 t, %1; cvt.u32.u64 %0, t; }"
        : "=r"(a) : "l"(p));
    return a;
}
DI uint32_t tf32r(float f) {   // round-to-nearest tf32 (unbiased)
    uint32_t r;
    asm("cvt.rna.tf32.f32 %0, %1;" : "=r"(r) : "f"(f));
    return r;
}
DI void cp16(uint32_t dst, const float* src) {
    asm volatile("cp.async.cg.shared.global [%0], [%1], 16;"
                 :: "r"(dst), "l"(src));
}
DI void cp16z(uint32_t dst, const float* src, int valid) {  // zero-fill if !valid
    asm volatile("cp.async.cg.shared.global [%0], [%1], 16, %2;"
                 :: "r"(dst), "l"(src), "r"(valid ? 16 : 0));
}
DI void cp_commit() { asm volatile("cp.async.commit_group;"); }
DI void cp_wait1()  { asm volatile("cp.async.wait_group 1;"); }

DI void mma8(float c[4], const uint32_t a[4], const uint32_t b[2]) {
    asm volatile(
        "mma.sync.aligned.m16n8k8.row.col.f32.tf32.tf32.f32 "
        "{%0,%1,%2,%3}, {%4,%5,%6,%7}, {%8,%9}, {%0,%1,%2,%3};"
        : "+f"(c[0]), "+f"(c[1]), "+f"(c[2]), "+f"(c[3])
        : "r"(a[0]), "r"(a[1]), "r"(a[2]), "r"(a[3]), "r"(b[0]), "r"(b[1]));
}

// One BK=32 chunk of warp-MMA over a stage's SMEM tiles.
DI void compute_chunk(const float* __restrict__ as, const float* __restrict__ bs,
                      int wm, int wn, int g, int t4, float acc[4][4][4]) {
#pragma unroll
    for (int ks = 0; ks < 4; ks++) {
        const int kc = ks * 8 + t4;
        uint32_t af[4][4], bf[4][2];
#pragma unroll
        for (int mf = 0; mf < 4; mf++) {
            const float* ap = as + (wm + mf * 16 + g) * APAD + kc;
            af[mf][0] = tf32r(ap[0]);
            af[mf][1] = tf32r(ap[8 * APAD]);
            af[mf][2] = tf32r(ap[4]);
            af[mf][3] = tf32r(ap[8 * APAD + 4]);
        }
#pragma unroll
        for (int nf = 0; nf < 4; nf++) {
            const float* bp = bs + kc * BPAD + wn + nf * 8 + g;
            bf[nf][0] = tf32r(bp[0]);
            bf[nf][1] = tf32r(bp[4 * BPAD]);
        }
#pragma unroll
        for (int mf = 0; mf < 4; mf++)
#pragma unroll
            for (int nf = 0; nf < 4; nf++)
                mma8(acc[mf][nf], af[mf], bf[nf]);
    }
}

// ---------------------------------------------------------------------------
// mma_gemm: C[m, n0:n0+128] = A_row(m)[0:K] @ W[K,512] + biasVec (opt ReLU)
// A_row(m) = A + b*batchStride + t*rowStride,  m = b*rowsPerBatch + t.
// ---------------------------------------------------------------------------
template<bool RELU>
__global__ void __launch_bounds__(256) mma_gemm(
    const float* __restrict__ A, int rowsPerBatch, int rowStride, long batchStride,
    const float* __restrict__ W, int K,
    const float* __restrict__ biasVec, float* __restrict__ C, int M)
{
    extern __shared__ float sm[];
    const uint32_t sb = smem_u32(sm);
    const int tid = threadIdx.x, lane = tid & 31, wid = tid >> 5;
    const int m0 = blockIdx.y * BM, n0 = blockIdx.x * BN;

    // A gmem mapping: row am = tid>>1, k-half ah = (tid&1)*16
    const int am = tid >> 1, ah = (tid & 1) * 16;
    const float* aptr;
    {
        int mm = m0 + am; if (mm >= M) mm = M - 1;   // clamp; store guarded
        int b = mm / rowsPerBatch, t = mm - b * rowsPerBatch;
        aptr = A + (long)b * batchStride + (long)t * rowStride + ah;
    }
    const uint32_t adst0 = sb + (uint32_t)(am * APAD + ah) * 4u;

    // B gmem mapping: k-row bk = tid>>3, n-chunk bn = (tid&7)*16
    const int bk = tid >> 3, bn = (tid & 7) * 16;
    const float* bptr = W + (long)bk * FF + n0 + bn;
    const uint32_t bdst0 = sb + (uint32_t)(AS_F + bk * BPAD + bn) * 4u;

    const int NC = K / BK;

#define LOAD_STAGE(i)                                                          \
    do {                                                                       \
        const uint32_t off = (uint32_t)(((i) % NSTAGE) * STG_F) * 4u;          \
        const float* asrc = aptr + (i) * BK;                                   \
        _Pragma("unroll")                                                      \
        for (int q = 0; q < 4; q++) cp16(adst0 + off + q * 16, asrc + q * 4);  \
        const float* bsrc = bptr + (long)(i) * BK * FF;                        \
        _Pragma("unroll")                                                      \
        for (int q = 0; q < 4; q++) cp16(bdst0 + off + q * 16, bsrc + q * 4);  \
        cp_commit();                                                           \
    } while (0)

    float acc[4][4][4];
#pragma unroll
    for (int a = 0; a < 4; a++)
#pragma unroll
        for (int b = 0; b < 4; b++)
#pragma unroll
            for (int c = 0; c < 4; c++) acc[a][b][c] = 0.f;

    const int wm = (wid & 1) * 64, wn = (wid >> 1) * 32;
    const int g = lane >> 2, t4 = lane & 3;

    LOAD_STAGE(0);
    LOAD_STAGE(1);

    for (int i = 0; i < NC; i++) {
        cp_wait1();
        __syncthreads();
        if (i + 2 < NC) LOAD_STAGE(i + 2); else cp_commit();
        const float* as = sm + (i % NSTAGE) * STG_F;
        compute_chunk(as, as + AS_F, wm, wn, g, t4, acc);
        __syncthreads();
    }
#undef LOAD_STAGE

    // epilogue
    float bv[4][2];
#pragma unroll
    for (int nf = 0; nf < 4; nf++) {
        int nc = n0 + wn + nf * 8 + t4 * 2;
        bv[nf][0] = biasVec[nc]; bv[nf][1] = biasVec[nc + 1];
    }
#pragma unroll
    for (int mf = 0; mf < 4; mf++)
#pragma unroll
        for (int hh = 0; hh < 2; hh++) {
            int m = m0 + wm + mf * 16 + g + hh * 8;
            if (m < M) {
                float* crow = C + (long)m * FF + n0;
#pragma unroll
                for (int nf = 0; nf < 4; nf++) {
                    float2 v;
                    v.x = acc[mf][nf][hh * 2 + 0] + bv[nf][0];
                    v.y = acc[mf][nf][hh * 2 + 1] + bv[nf][1];
                    if (RELU) { v.x = fmaxf(v.x, 0.f); v.y = fmaxf(v.y, 0.f); }
                    *(float2*)(crow + wn + nf * 8 + t4 * 2) = v;
                }
            }
        }
}

// ---------------------------------------------------------------------------
// mma_final: out[b,m,n] = sum_{k=1..4095} x[b,m,k]*wts[b,k-1,n] + biasM[b,m,n]
// B row kg reads wts[kg-1]; kg==0 zero-filled via cp.async src_size=0.
// grid = (4 n-tiles, 4 m-tiles, 8 batches), K=4096 -> 128 chunks.
// ---------------------------------------------------------------------------
__global__ void __launch_bounds__(256) mma_final(
    const float* __restrict__ x, const float* __restrict__ wts,
    const float* __restrict__ biasM, float* __restrict__ out)
{
    extern __shared__ float sm[];
    const uint32_t sb = smem_u32(sm);
    const int tid = threadIdx.x, lane = tid & 31, wid = tid >> 5;
    const int bz = blockIdx.z;
    const int m0 = blockIdx.y * BM, n0 = blockIdx.x * BN;

    const int am = tid >> 1, ah = (tid & 1) * 16;
    const float* aptr = x + (long)(bz * 512 + m0 + am) * TT + ah;
    const uint32_t adst0 = sb + (uint32_t)(am * APAD + ah) * 4u;

    const int bk = tid >> 3, bn = (tid & 7) * 16;
    const float* wb = wts + (long)bz * TT * FF + n0 + bn;
    const uint32_t bdst0 = sb + (uint32_t)(AS_F + bk * BPAD + bn) * 4u;

    const int NC = TT / BK;   // 128

#define LOAD_STAGE_F(i)                                                        \
    do {                                                                       \
        const uint32_t off = (uint32_t)(((i) % NSTAGE) * STG_F) * 4u;          \
        const float* asrc = aptr + (i) * BK;                                   \
        _Pragma("unroll")                                                      \
        for (int q = 0; q < 4; q++) cp16(adst0 + off + q * 16, asrc + q * 4);  \
        const int kg = (i) * BK + bk;                                          \
        const float* bsrc = wb + (long)(kg > 0 ? kg - 1 : 0) * FF;             \
        _Pragma("unroll")                                                      \
        for (int q = 0; q < 4; q++)                                            \
            cp16z(bdst0 + off + q * 16, bsrc + q * 4, kg > 0);                 \
        cp_commit();                                                           \
    } while (0)

    float acc[4][4][4];
#pragma unroll
    for (int a = 0; a < 4; a++)
#pragma unroll
        for (int b = 0; b < 4; b++)
#pragma unroll
            for (int c = 0; c < 4; c++) acc[a][b][c] = 0.f;

    const int wm = (wid & 1) * 64, wn = (wid >> 1) * 32;
    const int g = lane >> 2, t4 = lane & 3;

    LOAD_STAGE_F(0);
    LOAD_STAGE_F(1);

    for (int i = 0; i < NC; i++) {
        cp_wait1();
        __syncthreads();
        if (i + 2 < NC) LOAD_STAGE_F(i + 2); else cp_commit();
        const float* as = sm + (i % NSTAGE) * STG_F;
        compute_chunk(as, as + AS_F, wm, wn, g, t4, acc);
        __syncthreads();
    }
#undef LOAD_STAGE_F

    // epilogue: add bias matrix, write out
#pragma unroll
    for (int mf = 0; mf < 4; mf++)
#pragma unroll
        for (int hh = 0; hh < 2; hh++) {
            int m = m0 + wm + mf * 16 + g + hh * 8;
            const long base = ((long)bz * 512 + m) * FF + n0;
#pragma unroll
            for (int nf = 0; nf < 4; nf++) {
                int nc = wn + nf * 8 + t4 * 2;
                float2 bm = *(const float2*)(biasM + base + nc);
                float2 v;
                v.x = acc[mf][nf][hh * 2 + 0] + bm.x;
                v.y = acc[mf][nf][hh * 2 + 1] + bm.y;
                *(float2*)(out + base + nc) = v;
            }
        }
}

// ---------------------------------------------------------------------------
extern "C" void kernel_launch(void* const* d_in, const int* in_sizes, int n_in,
                              void* d_out, int out_size)
{
    const float* x   = (const float*)d_in[0];
    const float* z   = (const float*)d_in[1];
    const float* ww1 = (const float*)d_in[2];
    const float* wb1 = (const float*)d_in[3];
    const float* ww2 = (const float*)d_in[4];
    const float* wb2 = (const float*)d_in[5];
    const float* bw1 = (const float*)d_in[6];
    const float* bb1 = (const float*)d_in[7];
    const float* bw2 = (const float*)d_in[8];
    const float* bb2 = (const float*)d_in[9];
    float* out = (float*)d_out;

    float *h1w, *h1b, *wts, *bias;
    cudaGetSymbolAddress((void**)&h1w,  g_h1w);
    cudaGetSymbolAddress((void**)&h1b,  g_h1b);
    cudaGetSymbolAddress((void**)&wts,  g_wts);
    cudaGetSymbolAddress((void**)&bias, g_bias);

    cudaFuncSetAttribute(mma_gemm<true>,  cudaFuncAttributeMaxDynamicSharedMemorySize, SMEM_BYTES);
    cudaFuncSetAttribute(mma_gemm<false>, cudaFuncAttributeMaxDynamicSharedMemorySize, SMEM_BYTES);
    cudaFuncSetAttribute(mma_final,       cudaFuncAttributeMaxDynamicSharedMemorySize, SMEM_BYTES);

    dim3 thr(256);

    // weights conv1 + ReLU: M = 8*4097, K = 256
    mma_gemm<true><<<dim3(FF / BN, (BATCH * T1W + BM - 1) / BM), thr, SMEM_BYTES>>>(
        z, T1W, ZD, (long)TZv * ZD, ww1, 2 * ZD, wb1, h1w, BATCH * T1W);

    // bias conv1 + ReLU (truncated): M = 8*513, K = 256
    mma_gemm<true><<<dim3(FF / BN, (BATCH * T1B + BM - 1) / BM), thr, SMEM_BYTES>>>(
        z, T1B, ZD, (long)TZv * ZD, bw1, 2 * ZD, bb1, h1b, BATCH * T1B);

    // weights conv2: M = 8*4096, K = 1024
    mma_gemm<false><<<dim3(FF / BN, (BATCH * TT) / BM), thr, SMEM_BYTES>>>(
        h1w, TT, FF, (long)T1W * FF, ww2, 2 * FF, wb2, wts, BATCH * TT);

    // bias conv2 (truncated): M = 8*512, K = 1024
    mma_gemm<false><<<dim3(FF / BN, (BATCH * 512) / BM), thr, SMEM_BYTES>>>(
        h1b, 512, FF, (long)T1B * FF, bw2, 2 * FF, bb2, bias, BATCH * 512);

    // final batched GEMM: per-batch 512x512 @ K=4096(shifted) + bias matrix
    mma_final<<<dim3(FF / BN, 512 / BM, BATCH), thr, SMEM_BYTES>>>(x, wts, bias, out);
}

// round 12
// speedup vs baseline: 2.5093x; 1.0318x over previous
#include <cuda_runtime.h>
#include <cstdint>

// ---------------------------------------------------------------------------
// HyperConv via warp-level mma.sync tf32 (compute_103-safe: NO tcgen05).
//   out[b,c,f] = sum_{k=1..4095} x[b,c,k] * W[b,k-1,f] + bias[b,c,f]
//   W    = conv2(relu(conv1(z,ww1)+wb1), ww2)+wb2   (T=4096 steps)
//   bias = same with bw*/bb*, only first 512 steps needed
// KS=2 convs over contiguous z rows are plain GEMMs with contiguous K=2*Cin.
// R11 changes: all multiplied operands pre-converted to tf32 bit patterns
// (no cvt in the mainloop), 2-stage cp.async pipeline (70.6KB smem) for
// 2+ CTAs/SM.
// ---------------------------------------------------------------------------

namespace {
constexpr int BATCH = 8;
constexpr int TT    = 4096;
constexpr int TZv   = 4098;
constexpr int ZD    = 128;
constexpr int FF    = 512;
constexpr int T1W   = 4097;   // hidden steps, weights path
constexpr int T1B   = 513;    // hidden steps, bias path

constexpr int BM = 128, BN = 128, BK = 32;
constexpr int APAD = 36;                 // A smem row length (32 data + 4 pad)
constexpr int BPAD = 132;                // B smem row length (128 data + 4 pad)
constexpr int AS_F = BM * APAD;          // 4608 words
constexpr int BS_F = BK * BPAD;          // 4224 words
constexpr int STG_F = AS_F + BS_F;       // 8832 words / stage
constexpr int NSTAGE = 2;
constexpr int SMEM_BYTES = NSTAGE * STG_F * 4;   // 70656 B
}

// Scratch (device globals; no allocations allowed). All "t" buffers hold
// tf32 bit patterns (RNA-rounded) stored as 32-bit words.
__device__ __align__(256) uint32_t g_h1w[BATCH * T1W * FF];   // ~67 MB (tf32)
__device__ __align__(256) uint32_t g_h1b[BATCH * T1B * FF];   // ~8.4 MB (tf32)
__device__ __align__(256) uint32_t g_wts[BATCH * TT  * FF];   // ~67 MB (tf32)
__device__ __align__(256) float    g_bias[BATCH * 512 * FF];  // ~8.4 MB (fp32)
__device__ __align__(256) uint32_t g_xtf[BATCH * 512 * TT];   // ~67 MB (tf32)
__device__ __align__(256) uint32_t g_ztf[BATCH * TZv * ZD];   // ~17 MB (tf32)
__device__ __align__(256) uint32_t g_ww1t[2 * ZD * FF];
__device__ __align__(256) uint32_t g_ww2t[2 * FF * FF];
__device__ __align__(256) uint32_t g_bw1t[2 * ZD * FF];
__device__ __align__(256) uint32_t g_bw2t[2 * FF * FF];

#define DI __device__ __forceinline__

DI uint32_t smem_u32(const void* p) {
    uint32_t a;
    asm("{ .reg .u64 t; cvta.to.shared.u64 t, %1; cvt.u32.u64 %0, t; }"
        : "=r"(a) : "l"(p));
    return a;
}
DI uint32_t tf32r(float f) {   // round-to-nearest tf32 (unbiased)
    uint32_t r;
    asm("cvt.rna.tf32.f32 %0, %1;" : "=r"(r) : "f"(f));
    return r;
}
DI void cp16(uint32_t dst, const void* src) {
    asm volatile("cp.async.cg.shared.global [%0], [%1], 16;"
                 :: "r"(dst), "l"(src));
}
DI void cp16z(uint32_t dst, const void* src, int valid) {  // zero-fill if !valid
    asm volatile("cp.async.cg.shared.global [%0], [%1], 16, %2;"
                 :: "r"(dst), "l"(src), "r"(valid ? 16 : 0));
}
DI void cp_commit() { asm volatile("cp.async.commit_group;"); }
DI void cp_wait1()  { asm volatile("cp.async.wait_group 1;"); }

DI void mma8(float c[4], const uint32_t a[4], const uint32_t b[2]) {
    asm volatile(
        "mma.sync.aligned.m16n8k8.row.col.f32.tf32.tf32.f32 "
        "{%0,%1,%2,%3}, {%4,%5,%6,%7}, {%8,%9}, {%0,%1,%2,%3};"
        : "+f"(c[0]), "+f"(c[1]), "+f"(c[2]), "+f"(c[3])
        : "r"(a[0]), "r"(a[1]), "r"(a[2]), "r"(a[3]), "r"(b[0]), "r"(b[1]));
}

// One BK=32 chunk of warp-MMA over a stage's SMEM tiles (pre-converted tf32).
DI void compute_chunk(const uint32_t* __restrict__ as, const uint32_t* __restrict__ bs,
                      int wm, int wn, int g, int t4, float acc[4][4][4]) {
#pragma unroll
    for (int ks = 0; ks < 4; ks++) {
        const int kc = ks * 8 + t4;
        uint32_t af[4][4], bf[4][2];
#pragma unroll
        for (int mf = 0; mf < 4; mf++) {
            const uint32_t* ap = as + (wm + mf * 16 + g) * APAD + kc;
            af[mf][0] = ap[0];
            af[mf][1] = ap[8 * APAD];
            af[mf][2] = ap[4];
            af[mf][3] = ap[8 * APAD + 4];
        }
#pragma unroll
        for (int nf = 0; nf < 4; nf++) {
            const uint32_t* bp = bs + kc * BPAD + wn + nf * 8 + g;
            bf[nf][0] = bp[0];
            bf[nf][1] = bp[4 * BPAD];
        }
#pragma unroll
        for (int mf = 0; mf < 4; mf++)
#pragma unroll
            for (int nf = 0; nf < 4; nf++)
                mma8(acc[mf][nf], af[mf], bf[nf]);
    }
}

// Elementwise fp32 -> tf32-bits converter (grid-stride, float4).
__global__ void cvt_tf32_kernel(const float4* __restrict__ in,
                                uint4* __restrict__ out, int n4) {
    for (int i = blockIdx.x * blockDim.x + threadIdx.x; i < n4;
         i += gridDim.x * blockDim.x) {
        float4 v = in[i];
        uint4 o;
        o.x = tf32r(v.x); o.y = tf32r(v.y); o.z = tf32r(v.z); o.w = tf32r(v.w);
        out[i] = o;
    }
}

// ---------------------------------------------------------------------------
// mma_gemm: C[m, n0:n0+128] = A_row(m)[0:K] @ W[K,512] + biasVec
// A_row(m) = A + b*batchStride + t*rowStride,  m = b*rowsPerBatch + t.
// A, W hold tf32 bit patterns. CVTOUT: round output to tf32 bits (next-stage
// operand); otherwise plain fp32 floats.
// ---------------------------------------------------------------------------
template<bool RELU, bool CVTOUT>
__global__ void __launch_bounds__(256, 2) mma_gemm(
    const uint32_t* __restrict__ A, int rowsPerBatch, int rowStride, long batchStride,
    const uint32_t* __restrict__ W, int K,
    const float* __restrict__ biasVec, uint32_t* __restrict__ C, int M)
{
    extern __shared__ uint32_t sm[];
    const uint32_t sb = smem_u32(sm);
    const int tid = threadIdx.x, lane = tid & 31, wid = tid >> 5;
    const int m0 = blockIdx.y * BM, n0 = blockIdx.x * BN;

    // A gmem mapping: row am = tid>>1, k-half ah = (tid&1)*16
    const int am = tid >> 1, ah = (tid & 1) * 16;
    const uint32_t* aptr;
    {
        int mm = m0 + am; if (mm >= M) mm = M - 1;   // clamp; store guarded
        int b = mm / rowsPerBatch, t = mm - b * rowsPerBatch;
        aptr = A + (long)b * batchStride + (long)t * rowStride + ah;
    }
    const uint32_t adst0 = sb + (uint32_t)(am * APAD + ah) * 4u;

    // B gmem mapping: k-row bk = tid>>3, n-chunk bn = (tid&7)*16
    const int bk = tid >> 3, bn = (tid & 7) * 16;
    const uint32_t* bptr = W + (long)bk * FF + n0 + bn;
    const uint32_t bdst0 = sb + (uint32_t)(AS_F + bk * BPAD + bn) * 4u;

    const int NC = K / BK;

#define LOAD_STAGE(i)                                                          \
    do {                                                                       \
        const uint32_t off = (uint32_t)(((i) & 1) * STG_F) * 4u;               \
        const uint32_t* asrc = aptr + (i) * BK;                                \
        _Pragma("unroll")                                                      \
        for (int q = 0; q < 4; q++) cp16(adst0 + off + q * 16, asrc + q * 4);  \
        const uint32_t* bsrc = bptr + (long)(i) * BK * FF;                     \
        _Pragma("unroll")                                                      \
        for (int q = 0; q < 4; q++) cp16(bdst0 + off + q * 16, bsrc + q * 4);  \
        cp_commit();                                                           \
    } while (0)

    float acc[4][4][4];
#pragma unroll
    for (int a = 0; a < 4; a++)
#pragma unroll
        for (int b = 0; b < 4; b++)
#pragma unroll
            for (int c = 0; c < 4; c++) acc[a][b][c] = 0.f;

    const int wm = (wid & 1) * 64, wn = (wid >> 1) * 32;
    const int g = lane >> 2, t4 = lane & 3;

    LOAD_STAGE(0);

    for (int i = 0; i < NC; i++) {
        if (i + 1 < NC) LOAD_STAGE(i + 1); else cp_commit();
        cp_wait1();                 // stage i complete; stage i+1 in flight
        __syncthreads();
        const uint32_t* as = sm + (i & 1) * STG_F;
        compute_chunk(as, as + AS_F, wm, wn, g, t4, acc);
        __syncthreads();            // done with slot (i&1) before reload
    }
#undef LOAD_STAGE

    // epilogue
    float bv[4][2];
#pragma unroll
    for (int nf = 0; nf < 4; nf++) {
        int nc = n0 + wn + nf * 8 + t4 * 2;
        bv[nf][0] = biasVec[nc]; bv[nf][1] = biasVec[nc + 1];
    }
#pragma unroll
    for (int mf = 0; mf < 4; mf++)
#pragma unroll
        for (int hh = 0; hh < 2; hh++) {
            int m = m0 + wm + mf * 16 + g + hh * 8;
            if (m < M) {
                uint32_t* crow = C + (long)m * FF + n0;
#pragma unroll
                for (int nf = 0; nf < 4; nf++) {
                    float vx = acc[mf][nf][hh * 2 + 0] + bv[nf][0];
                    float vy = acc[mf][nf][hh * 2 + 1] + bv[nf][1];
                    if (RELU) { vx = fmaxf(vx, 0.f); vy = fmaxf(vy, 0.f); }
                    uint2 o;
                    if (CVTOUT) { o.x = tf32r(vx); o.y = tf32r(vy); }
                    else        { o.x = __float_as_uint(vx); o.y = __float_as_uint(vy); }
                    *(uint2*)(crow + wn + nf * 8 + t4 * 2) = o;
                }
            }
        }
}

// ---------------------------------------------------------------------------
// mma_final: out[b,m,n] = sum_{k=1..4095} x[b,m,k]*wts[b,k-1,n] + biasM[b,m,n]
// A = pre-converted x (tf32 bits), B row kg reads wts[kg-1]; kg==0 zero-fill.
// grid = (4 n-tiles, 4 m-tiles, 8 batches), K=4096 -> 128 chunks.
// ---------------------------------------------------------------------------
__global__ void __launch_bounds__(256, 2) mma_final(
    const uint32_t* __restrict__ x, const uint32_t* __restrict__ wts,
    const float* __restrict__ biasM, float* __restrict__ out)
{
    extern __shared__ uint32_t sm[];
    const uint32_t sb = smem_u32(sm);
    const int tid = threadIdx.x, lane = tid & 31, wid = tid >> 5;
    const int bz = blockIdx.z;
    const int m0 = blockIdx.y * BM, n0 = blockIdx.x * BN;

    const int am = tid >> 1, ah = (tid & 1) * 16;
    const uint32_t* aptr = x + (long)(bz * 512 + m0 + am) * TT + ah;
    const uint32_t adst0 = sb + (uint32_t)(am * APAD + ah) * 4u;

    const int bk = tid >> 3, bn = (tid & 7) * 16;
    const uint32_t* wb = wts + (long)bz * TT * FF + n0 + bn;
    const uint32_t bdst0 = sb + (uint32_t)(AS_F + bk * BPAD + bn) * 4u;

    const int NC = TT / BK;   // 128

#define LOAD_STAGE_F(i)                                                        \
    do {                                                                       \
        const uint32_t off = (uint32_t)(((i) & 1) * STG_F) * 4u;               \
        const uint32_t* asrc = aptr + (i) * BK;                                \
        _Pragma("unroll")                                                      \
        for (int q = 0; q < 4; q++) cp16(adst0 + off + q * 16, asrc + q * 4);  \
        const int kg = (i) * BK + bk;                                          \
        const uint32_t* bsrc = wb + (long)(kg > 0 ? kg - 1 : 0) * FF;          \
        _Pragma("unroll")                                                      \
        for (int q = 0; q < 4; q++)                                            \
            cp16z(bdst0 + off + q * 16, bsrc + q * 4, kg > 0);                 \
        cp_commit();                                                           \
    } while (0)

    float acc[4][4][4];
#pragma unroll
    for (int a = 0; a < 4; a++)
#pragma unroll
        for (int b = 0; b < 4; b++)
#pragma unroll
            for (int c = 0; c < 4; c++) acc[a][b][c] = 0.f;

    const int wm = (wid & 1) * 64, wn = (wid >> 1) * 32;
    const int g = lane >> 2, t4 = lane & 3;

    LOAD_STAGE_F(0);

    for (int i = 0; i < NC; i++) {
        if (i + 1 < NC) LOAD_STAGE_F(i + 1); else cp_commit();
        cp_wait1();
        __syncthreads();
        const uint32_t* as = sm + (i & 1) * STG_F;
        compute_chunk(as, as + AS_F, wm, wn, g, t4, acc);
        __syncthreads();
    }
#undef LOAD_STAGE_F

    // epilogue: add bias matrix, write out
#pragma unroll
    for (int mf = 0; mf < 4; mf++)
#pragma unroll
        for (int hh = 0; hh < 2; hh++) {
            int m = m0 + wm + mf * 16 + g + hh * 8;
            const long base = ((long)bz * 512 + m) * FF + n0;
#pragma unroll
            for (int nf = 0; nf < 4; nf++) {
                int nc = wn + nf * 8 + t4 * 2;
                float2 bm = *(const float2*)(biasM + base + nc);
                float2 v;
                v.x = acc[mf][nf][hh * 2 + 0] + bm.x;
                v.y = acc[mf][nf][hh * 2 + 1] + bm.y;
                *(float2*)(out + base + nc) = v;
            }
        }
}

// ---------------------------------------------------------------------------
extern "C" void kernel_launch(void* const* d_in, const int* in_sizes, int n_in,
                              void* d_out, int out_size)
{
    const float* x   = (const float*)d_in[0];
    const float* z   = (const float*)d_in[1];
    const float* ww1 = (const float*)d_in[2];
    const float* wb1 = (const float*)d_in[3];
    const float* ww2 = (const float*)d_in[4];
    const float* wb2 = (const float*)d_in[5];
    const float* bw1 = (const float*)d_in[6];
    const float* bb1 = (const float*)d_in[7];
    const float* bw2 = (const float*)d_in[8];
    const float* bb2 = (const float*)d_in[9];
    float* out = (float*)d_out;

    uint32_t *h1w, *h1b, *wts, *xtf, *ztf, *ww1t, *ww2t, *bw1t, *bw2t;
    float *bias;
    cudaGetSymbolAddress((void**)&h1w,  g_h1w);
    cudaGetSymbolAddress((void**)&h1b,  g_h1b);
    cudaGetSymbolAddress((void**)&wts,  g_wts);
    cudaGetSymbolAddress((void**)&bias, g_bias);
    cudaGetSymbolAddress((void**)&xtf,  g_xtf);
    cudaGetSymbolAddress((void**)&ztf,  g_ztf);
    cudaGetSymbolAddress((void**)&ww1t, g_ww1t);
    cudaGetSymbolAddress((void**)&ww2t, g_ww2t);
    cudaGetSymbolAddress((void**)&bw1t, g_bw1t);
    cudaGetSymbolAddress((void**)&bw2t, g_bw2t);

    cudaFuncSetAttribute(mma_gemm<true, true>,
                         cudaFuncAttributeMaxDynamicSharedMemorySize, SMEM_BYTES);
    cudaFuncSetAttribute(mma_gemm<false, true>,
                         cudaFuncAttributeMaxDynamicSharedMemorySize, SMEM_BYTES);
    cudaFuncSetAttribute(mma_gemm<false, false>,
                         cudaFuncAttributeMaxDynamicSharedMemorySize, SMEM_BYTES);
    cudaFuncSetAttribute(mma_final,
                         cudaFuncAttributeMaxDynamicSharedMemorySize, SMEM_BYTES);

    dim3 thr(256);

    // Pre-convert multiplied operands to tf32 bit patterns.
    auto cvt = [&](const float* in, uint32_t* o, long n) {
        int n4 = (int)(n / 4);
        int grid = (n4 + 255) / 256; if (grid > 8192) grid = 8192;
        cvt_tf32_kernel<<<grid, 256>>>((const float4*)in, (uint4*)o, n4);
    };
    cvt(x,   xtf,  (long)BATCH * 512 * TT);
    cvt(z,   ztf,  (long)BATCH * TZv * ZD);
    cvt(ww1, ww1t, 2 * ZD * FF);
    cvt(ww2, ww2t, 2 * FF * FF);
    cvt(bw1, bw1t, 2 * ZD * FF);
    cvt(bw2, bw2t, 2 * FF * FF);

    // weights conv1 + ReLU: M = 8*4097, K = 256  (out: tf32 bits)
    mma_gemm<true, true><<<dim3(FF / BN, (BATCH * T1W + BM - 1) / BM), thr, SMEM_BYTES>>>(
        ztf, T1W, ZD, (long)TZv * ZD, ww1t, 2 * ZD, wb1, h1w, BATCH * T1W);

    // bias conv1 + ReLU (truncated): M = 8*513, K = 256  (out: tf32 bits)
    mma_gemm<true, true><<<dim3(FF / BN, (BATCH * T1B + BM - 1) / BM), thr, SMEM_BYTES>>>(
        ztf, T1B, ZD, (long)TZv * ZD, bw1t, 2 * ZD, bb1, h1b, BATCH * T1B);

    // weights conv2: M = 8*4096, K = 1024  (out: tf32 bits, B of final GEMM)
    mma_gemm<false, true><<<dim3(FF / BN, (BATCH * TT) / BM), thr, SMEM_BYTES>>>(
        h1w, TT, FF, (long)T1W * FF, ww2t, 2 * FF, wb2, wts, BATCH * TT);

    // bias conv2 (truncated): M = 8*512, K = 1024  (out: fp32, added only)
    mma_gemm<false, false><<<dim3(FF / BN, (BATCH * 512) / BM), thr, SMEM_BYTES>>>(
        h1b, 512, FF, (long)T1B * FF, bw2t, 2 * FF, bb2, (uint32_t*)bias, BATCH * 512);

    // final batched GEMM: per-batch 512x512 @ K=4096(shifted) + bias matrix
    mma_final<<<dim3(FF / BN, 512 / BM, BATCH), thr, SMEM_BYTES>>>(xtf, wts, bias, out);
}

// round 13
// speedup vs baseline: 2.6708x; 1.0644x over previous
#include <cuda_runtime.h>
#include <cstdint>

// ---------------------------------------------------------------------------
// HyperConv via warp-level mma.sync tf32 (compute_103-safe: NO tcgen05).
//   out[b,c,f] = sum_{k=1..4095} x[b,c,k] * W[b,k-1,f] + bias[b,c,f]
//   W    = conv2(relu(conv1(z,ww1)+wb1), ww2)+wb2   (T=4096 steps)
//   bias = same with bw*/bb*, only first 512 steps needed
// R12 changes: BPAD 132->136 (conflict-free B LDS), explicit double-buffered
// fragment pipeline inside each BK=32 chunk (hide LDS latency behind MMAs).
// ---------------------------------------------------------------------------

namespace {
constexpr int BATCH = 8;
constexpr int TT    = 4096;
constexpr int TZv   = 4098;
constexpr int ZD    = 128;
constexpr int FF    = 512;
constexpr int T1W   = 4097;   // hidden steps, weights path
constexpr int T1B   = 513;    // hidden steps, bias path

constexpr int BM = 128, BN = 128, BK = 32;
constexpr int APAD = 36;                 // A smem row (32 data + 4 pad); 36%32=4 -> 4g+t4 distinct
constexpr int BPAD = 136;                // B smem row (128 data + 8 pad); 136%32=8 -> 8t4+g distinct
constexpr int AS_F = BM * APAD;          // 4608 words
constexpr int BS_F = BK * BPAD;          // 4352 words
constexpr int STG_F = AS_F + BS_F;       // 8960 words / stage
constexpr int NSTAGE = 2;
constexpr int SMEM_BYTES = NSTAGE * STG_F * 4;   // 71680 B (2 CTAs/SM fit)
}

// Scratch (device globals; no allocations allowed). "t" buffers hold tf32
// bit patterns (RNA-rounded) stored as 32-bit words.
__device__ __align__(256) uint32_t g_h1w[BATCH * T1W * FF];   // ~67 MB (tf32)
__device__ __align__(256) uint32_t g_h1b[BATCH * T1B * FF];   // ~8.4 MB (tf32)
__device__ __align__(256) uint32_t g_wts[BATCH * TT  * FF];   // ~67 MB (tf32)
__device__ __align__(256) float    g_bias[BATCH * 512 * FF];  // ~8.4 MB (fp32)
__device__ __align__(256) uint32_t g_xtf[BATCH * 512 * TT];   // ~67 MB (tf32)
__device__ __align__(256) uint32_t g_ztf[BATCH * TZv * ZD];   // ~17 MB (tf32)
__device__ __align__(256) uint32_t g_ww1t[2 * ZD * FF];
__device__ __align__(256) uint32_t g_ww2t[2 * FF * FF];
__device__ __align__(256) uint32_t g_bw1t[2 * ZD * FF];
__device__ __align__(256) uint32_t g_bw2t[2 * FF * FF];

#define DI __device__ __forceinline__

DI uint32_t smem_u32(const void* p) {
    uint32_t a;
    asm("{ .reg .u64 t; cvta.to.shared.u64 t, %1; cvt.u32.u64 %0, t; }"
        : "=r"(a) : "l"(p));
    return a;
}
DI uint32_t tf32r(float f) {   // round-to-nearest tf32 (unbiased)
    uint32_t r;
    asm("cvt.rna.tf32.f32 %0, %1;" : "=r"(r) : "f"(f));
    return r;
}
DI void cp16(uint32_t dst, const void* src) {
    asm volatile("cp.async.cg.shared.global [%0], [%1], 16;"
                 :: "r"(dst), "l"(src));
}
DI void cp16z(uint32_t dst, const void* src, int valid) {  // zero-fill if !valid
    asm volatile("cp.async.cg.shared.global [%0], [%1], 16, %2;"
                 :: "r"(dst), "l"(src), "r"(valid ? 16 : 0));
}
DI void cp_commit() { asm volatile("cp.async.commit_group;"); }
DI void cp_wait1()  { asm volatile("cp.async.wait_group 1;"); }

DI void mma8(float c[4], const uint32_t a[4], const uint32_t b[2]) {
    asm volatile(
        "mma.sync.aligned.m16n8k8.row.col.f32.tf32.tf32.f32 "
        "{%0,%1,%2,%3}, {%4,%5,%6,%7}, {%8,%9}, {%0,%1,%2,%3};"
        : "+f"(c[0]), "+f"(c[1]), "+f"(c[2]), "+f"(c[3])
        : "r"(a[0]), "r"(a[1]), "r"(a[2]), "r"(a[3]), "r"(b[0]), "r"(b[1]));
}

// Load one ks-step's fragments from SMEM into registers.
DI void load_frags(const uint32_t* __restrict__ as, const uint32_t* __restrict__ bs,
                   int ks, int wm, int wn, int g, int t4,
                   uint32_t af[4][4], uint32_t bf[4][2]) {
    const int kc = ks * 8 + t4;
#pragma unroll
    for (int mf = 0; mf < 4; mf++) {
        const uint32_t* ap = as + (wm + mf * 16 + g) * APAD + kc;
        af[mf][0] = ap[0];
        af[mf][1] = ap[8 * APAD];
        af[mf][2] = ap[4];
        af[mf][3] = ap[8 * APAD + 4];
    }
#pragma unroll
    for (int nf = 0; nf < 4; nf++) {
        const uint32_t* bp = bs + kc * BPAD + wn + nf * 8 + g;
        bf[nf][0] = bp[0];
        bf[nf][1] = bp[4 * BPAD];
    }
}

// One BK=32 chunk: 4 ks-steps, double-buffered fragments (LDS for ks+1
// overlaps the 16 MMAs of ks).
DI void compute_chunk(const uint32_t* __restrict__ as, const uint32_t* __restrict__ bs,
                      int wm, int wn, int g, int t4, float acc[4][4][4]) {
    uint32_t af[2][4][4], bf[2][4][2];
    load_frags(as, bs, 0, wm, wn, g, t4, af[0], bf[0]);
#pragma unroll
    for (int ks = 0; ks < 4; ks++) {
        const int cur = ks & 1;
        if (ks < 3)
            load_frags(as, bs, ks + 1, wm, wn, g, t4, af[cur ^ 1], bf[cur ^ 1]);
#pragma unroll
        for (int mf = 0; mf < 4; mf++)
#pragma unroll
            for (int nf = 0; nf < 4; nf++)
                mma8(acc[mf][nf], af[cur][mf], bf[cur][nf]);
    }
}

// Elementwise fp32 -> tf32-bits converter (grid-stride, float4).
__global__ void cvt_tf32_kernel(const float4* __restrict__ in,
                                uint4* __restrict__ out, int n4) {
    for (int i = blockIdx.x * blockDim.x + threadIdx.x; i < n4;
         i += gridDim.x * blockDim.x) {
        float4 v = in[i];
        uint4 o;
        o.x = tf32r(v.x); o.y = tf32r(v.y); o.z = tf32r(v.z); o.w = tf32r(v.w);
        out[i] = o;
    }
}

// ---------------------------------------------------------------------------
// mma_gemm: C[m, n0:n0+128] = A_row(m)[0:K] @ W[K,512] + biasVec
// A_row(m) = A + b*batchStride + t*rowStride,  m = b*rowsPerBatch + t.
// A, W hold tf32 bit patterns. CVTOUT: round output to tf32 bits.
// ---------------------------------------------------------------------------
template<bool RELU, bool CVTOUT>
__global__ void __launch_bounds__(256, 2) mma_gemm(
    const uint32_t* __restrict__ A, int rowsPerBatch, int rowStride, long batchStride,
    const uint32_t* __restrict__ W, int K,
    const float* __restrict__ biasVec, uint32_t* __restrict__ C, int M)
{
    extern __shared__ uint32_t sm[];
    const uint32_t sb = smem_u32(sm);
    const int tid = threadIdx.x, lane = tid & 31, wid = tid >> 5;
    const int m0 = blockIdx.y * BM, n0 = blockIdx.x * BN;

    // A gmem mapping: row am = tid>>1, k-half ah = (tid&1)*16
    const int am = tid >> 1, ah = (tid & 1) * 16;
    const uint32_t* aptr;
    {
        int mm = m0 + am; if (mm >= M) mm = M - 1;   // clamp; store guarded
        int b = mm / rowsPerBatch, t = mm - b * rowsPerBatch;
        aptr = A + (long)b * batchStride + (long)t * rowStride + ah;
    }
    const uint32_t adst0 = sb + (uint32_t)(am * APAD + ah) * 4u;

    // B gmem mapping: k-row bk = tid>>3, n-chunk bn = (tid&7)*16
    const int bk = tid >> 3, bn = (tid & 7) * 16;
    const uint32_t* bptr = W + (long)bk * FF + n0 + bn;
    const uint32_t bdst0 = sb + (uint32_t)(AS_F + bk * BPAD + bn) * 4u;

    const int NC = K / BK;

#define LOAD_STAGE(i)                                                          \
    do {                                                                       \
        const uint32_t off = (uint32_t)(((i) & 1) * STG_F) * 4u;               \
        const uint32_t* asrc = aptr + (i) * BK;                                \
        _Pragma("unroll")                                                      \
        for (int q = 0; q < 4; q++) cp16(adst0 + off + q * 16, asrc + q * 4);  \
        const uint32_t* bsrc = bptr + (long)(i) * BK * FF;                     \
        _Pragma("unroll")                                                      \
        for (int q = 0; q < 4; q++) cp16(bdst0 + off + q * 16, bsrc + q * 4);  \
        cp_commit();                                                           \
    } while (0)

    float acc[4][4][4];
#pragma unroll
    for (int a = 0; a < 4; a++)
#pragma unroll
        for (int b = 0; b < 4; b++)
#pragma unroll
            for (int c = 0; c < 4; c++) acc[a][b][c] = 0.f;

    const int wm = (wid & 1) * 64, wn = (wid >> 1) * 32;
    const int g = lane >> 2, t4 = lane & 3;

    LOAD_STAGE(0);

    for (int i = 0; i < NC; i++) {
        if (i + 1 < NC) LOAD_STAGE(i + 1); else cp_commit();
        cp_wait1();                 // stage i complete; stage i+1 in flight
        __syncthreads();
        const uint32_t* as = sm + (i & 1) * STG_F;
        compute_chunk(as, as + AS_F, wm, wn, g, t4, acc);
        __syncthreads();            // done with slot (i&1) before reload
    }
#undef LOAD_STAGE

    // epilogue
    float bv[4][2];
#pragma unroll
    for (int nf = 0; nf < 4; nf++) {
        int nc = n0 + wn + nf * 8 + t4 * 2;
        bv[nf][0] = biasVec[nc]; bv[nf][1] = biasVec[nc + 1];
    }
#pragma unroll
    for (int mf = 0; mf < 4; mf++)
#pragma unroll
        for (int hh = 0; hh < 2; hh++) {
            int m = m0 + wm + mf * 16 + g + hh * 8;
            if (m < M) {
                uint32_t* crow = C + (long)m * FF + n0;
#pragma unroll
                for (int nf = 0; nf < 4; nf++) {
                    float vx = acc[mf][nf][hh * 2 + 0] + bv[nf][0];
                    float vy = acc[mf][nf][hh * 2 + 1] + bv[nf][1];
                    if (RELU) { vx = fmaxf(vx, 0.f); vy = fmaxf(vy, 0.f); }
                    uint2 o;
                    if (CVTOUT) { o.x = tf32r(vx); o.y = tf32r(vy); }
                    else        { o.x = __float_as_uint(vx); o.y = __float_as_uint(vy); }
                    *(uint2*)(crow + wn + nf * 8 + t4 * 2) = o;
                }
            }
        }
}

// ---------------------------------------------------------------------------
// mma_final: out[b,m,n] = sum_{k=1..4095} x[b,m,k]*wts[b,k-1,n] + biasM[b,m,n]
// A = pre-converted x (tf32 bits), B row kg reads wts[kg-1]; kg==0 zero-fill.
// grid = (4 n-tiles, 4 m-tiles, 8 batches), K=4096 -> 128 chunks.
// ---------------------------------------------------------------------------
__global__ void __launch_bounds__(256, 2) mma_final(
    const uint32_t* __restrict__ x, const uint32_t* __restrict__ wts,
    const float* __restrict__ biasM, float* __restrict__ out)
{
    extern __shared__ uint32_t sm[];
    const uint32_t sb = smem_u32(sm);
    const int tid = threadIdx.x, lane = tid & 31, wid = tid >> 5;
    const int bz = blockIdx.z;
    const int m0 = blockIdx.y * BM, n0 = blockIdx.x * BN;

    const int am = tid >> 1, ah = (tid & 1) * 16;
    const uint32_t* aptr = x + (long)(bz * 512 + m0 + am) * TT + ah;
    const uint32_t adst0 = sb + (uint32_t)(am * APAD + ah) * 4u;

    const int bk = tid >> 3, bn = (tid & 7) * 16;
    const uint32_t* wb = wts + (long)bz * TT * FF + n0 + bn;
    const uint32_t bdst0 = sb + (uint32_t)(AS_F + bk * BPAD + bn) * 4u;

    const int NC = TT / BK;   // 128

#define LOAD_STAGE_F(i)                                                        \
    do {                                                                       \
        const uint32_t off = (uint32_t)(((i) & 1) * STG_F) * 4u;               \
        const uint32_t* asrc = aptr + (i) * BK;                                \
        _Pragma("unroll")                                                      \
        for (int q = 0; q < 4; q++) cp16(adst0 + off + q * 16, asrc + q * 4);  \
        const int kg = (i) * BK + bk;                                          \
        const uint32_t* bsrc = wb + (long)(kg > 0 ? kg - 1 : 0) * FF;          \
        _Pragma("unroll")                                                      \
        for (int q = 0; q < 4; q++)                                            \
            cp16z(bdst0 + off + q * 16, bsrc + q * 4, kg > 0);                 \
        cp_commit();                                                           \
    } while (0)

    float acc[4][4][4];
#pragma unroll
    for (int a = 0; a < 4; a++)
#pragma unroll
        for (int b = 0; b < 4; b++)
#pragma unroll
            for (int c = 0; c < 4; c++) acc[a][b][c] = 0.f;

    const int wm = (wid & 1) * 64, wn = (wid >> 1) * 32;
    const int g = lane >> 2, t4 = lane & 3;

    LOAD_STAGE_F(0);

    for (int i = 0; i < NC; i++) {
        if (i + 1 < NC) LOAD_STAGE_F(i + 1); else cp_commit();
        cp_wait1();
        __syncthreads();
        const uint32_t* as = sm + (i & 1) * STG_F;
        compute_chunk(as, as + AS_F, wm, wn, g, t4, acc);
        __syncthreads();
    }
#undef LOAD_STAGE_F

    // epilogue: add bias matrix, write out
#pragma unroll
    for (int mf = 0; mf < 4; mf++)
#pragma unroll
        for (int hh = 0; hh < 2; hh++) {
            int m = m0 + wm + mf * 16 + g + hh * 8;
            const long base = ((long)bz * 512 + m) * FF + n0;
#pragma unroll
            for (int nf = 0; nf < 4; nf++) {
                int nc = wn + nf * 8 + t4 * 2;
                float2 bm = *(const float2*)(biasM + base + nc);
                float2 v;
                v.x = acc[mf][nf][hh * 2 + 0] + bm.x;
                v.y = acc[mf][nf][hh * 2 + 1] + bm.y;
                *(float2*)(out + base + nc) = v;
            }
        }
}

// ---------------------------------------------------------------------------
extern "C" void kernel_launch(void* const* d_in, const int* in_sizes, int n_in,
                              void* d_out, int out_size)
{
    const float* x   = (const float*)d_in[0];
    const float* z   = (const float*)d_in[1];
    const float* ww1 = (const float*)d_in[2];
    const float* wb1 = (const float*)d_in[3];
    const float* ww2 = (const float*)d_in[4];
    const float* wb2 = (const float*)d_in[5];
    const float* bw1 = (const float*)d_in[6];
    const float* bb1 = (const float*)d_in[7];
    const float* bw2 = (const float*)d_in[8];
    const float* bb2 = (const float*)d_in[9];
    float* out = (float*)d_out;

    uint32_t *h1w, *h1b, *wts, *xtf, *ztf, *ww1t, *ww2t, *bw1t, *bw2t;
    float *bias;
    cudaGetSymbolAddress((void**)&h1w,  g_h1w);
    cudaGetSymbolAddress((void**)&h1b,  g_h1b);
    cudaGetSymbolAddress((void**)&wts,  g_wts);
    cudaGetSymbolAddress((void**)&bias, g_bias);
    cudaGetSymbolAddress((void**)&xtf,  g_xtf);
    cudaGetSymbolAddress((void**)&ztf,  g_ztf);
    cudaGetSymbolAddress((void**)&ww1t, g_ww1t);
    cudaGetSymbolAddress((void**)&ww2t, g_ww2t);
    cudaGetSymbolAddress((void**)&bw1t, g_bw1t);
    cudaGetSymbolAddress((void**)&bw2t, g_bw2t);

    cudaFuncSetAttribute(mma_gemm<true, true>,
                         cudaFuncAttributeMaxDynamicSharedMemorySize, SMEM_BYTES);
    cudaFuncSetAttribute(mma_gemm<false, true>,
                         cudaFuncAttributeMaxDynamicSharedMemorySize, SMEM_BYTES);
    cudaFuncSetAttribute(mma_gemm<false, false>,
                         cudaFuncAttributeMaxDynamicSharedMemorySize, SMEM_BYTES);
    cudaFuncSetAttribute(mma_final,
                         cudaFuncAttributeMaxDynamicSharedMemorySize, SMEM_BYTES);

    dim3 thr(256);

    // Pre-convert multiplied operands to tf32 bit patterns.
    auto cvt = [&](const float* in, uint32_t* o, long n) {
        int n4 = (int)(n / 4);
        int grid = (n4 + 255) / 256; if (grid > 8192) grid = 8192;
        cvt_tf32_kernel<<<grid, 256>>>((const float4*)in, (uint4*)o, n4);
    };
    cvt(x,   xtf,  (long)BATCH * 512 * TT);
    cvt(z,   ztf,  (long)BATCH * TZv * ZD);
    cvt(ww1, ww1t, 2 * ZD * FF);
    cvt(ww2, ww2t, 2 * FF * FF);
    cvt(bw1, bw1t, 2 * ZD * FF);
    cvt(bw2, bw2t, 2 * FF * FF);

    // weights conv1 + ReLU: M = 8*4097, K = 256  (out: tf32 bits)
    mma_gemm<true, true><<<dim3(FF / BN, (BATCH * T1W + BM - 1) / BM), thr, SMEM_BYTES>>>(
        ztf, T1W, ZD, (long)TZv * ZD, ww1t, 2 * ZD, wb1, h1w, BATCH * T1W);

    // bias conv1 + ReLU (truncated): M = 8*513, K = 256  (out: tf32 bits)
    mma_gemm<true, true><<<dim3(FF / BN, (BATCH * T1B + BM - 1) / BM), thr, SMEM_BYTES>>>(
        ztf, T1B, ZD, (long)TZv * ZD, bw1t, 2 * ZD, bb1, h1b, BATCH * T1B);

    // weights conv2: M = 8*4096, K = 1024  (out: tf32 bits, B of final GEMM)
    mma_gemm<false, true><<<dim3(FF / BN, (BATCH * TT) / BM), thr, SMEM_BYTES>>>(
        h1w, TT, FF, (long)T1W * FF, ww2t, 2 * FF, wb2, wts, BATCH * TT);

    // bias conv2 (truncated): M = 8*512, K = 1024  (out: fp32, added only)
    mma_gemm<false, false><<<dim3(FF / BN, (BATCH * 512) / BM), thr, SMEM_BYTES>>>(
        h1b, 512, FF, (long)T1B * FF, bw2t, 2 * FF, bb2, (uint32_t*)bias, BATCH * 512);

    // final batched GEMM: per-batch 512x512 @ K=4096(shifted) + bias matrix
    mma_final<<<dim3(FF / BN, 512 / BM, BATCH), thr, SMEM_BYTES>>>(xtf, wts, bias, out);
}

// round 14
// speedup vs baseline: 5.5730x; 2.0867x over previous
#include <cuda_runtime.h>
#include <cuda_fp16.h>
#include <cstdint>

// ---------------------------------------------------------------------------
// HyperConv via warp-level mma.sync fp16 m16n8k16 (compute_103-safe).
//   out[b,c,f] = sum_{k=1..4095} x[b,c,k] * W[b,k-1,f] + bias[b,c,f]
//   W    = conv2(relu(conv1(z,ww1)+wb1), ww2)+wb2   (T=4096 steps)
//   bias = same with bw*/bb*, only first 512 steps needed
// R13: pivot tf32 m16n8k8 -> fp16 m16n8k16 (same 10-bit significand, 2x
// MACs/instruction), ldmatrix fragment loads, halved smem/gmem traffic.
// ---------------------------------------------------------------------------

namespace {
constexpr int BATCH = 8;
constexpr int TT    = 4096;
constexpr int TZv   = 4098;
constexpr int ZD    = 128;
constexpr int FF    = 512;
constexpr int T1W   = 4097;   // hidden steps, weights path
constexpr int T1B   = 513;    // hidden steps, bias path

constexpr int BM = 128, BN = 128, BK = 32;
constexpr int APADH = 40;                // A smem row stride (halves): 80B -> ldmatrix conflict-free
constexpr int BPADH = 136;               // B smem row stride (halves): 272B -> ldmatrix conflict-free
constexpr int AS_H = BM * APADH;         // 5120 halves
constexpr int BS_H = BK * BPADH;         // 4352 halves
constexpr int STG_H = AS_H + BS_H;       // 9472 halves = 18944 B / stage
constexpr int SMEM_BYTES = 2 * STG_H * 2;   // 37888 B
}

// Scratch (device globals; no allocations allowed). fp16 operand buffers.
__device__ __align__(256) __half g_h1w[BATCH * T1W * FF];   // ~33.5 MB
__device__ __align__(256) __half g_h1b[BATCH * T1B * FF];   // ~4.2 MB
__device__ __align__(256) __half g_wts[BATCH * TT  * FF];   // ~33.5 MB
__device__ __align__(256) float  g_bias[BATCH * 512 * FF];  // ~8.4 MB (fp32, add-only)
__device__ __align__(256) __half g_xh [BATCH * 512 * TT];   // ~33.5 MB
__device__ __align__(256) __half g_zh [BATCH * TZv * ZD];   // ~8.4 MB
__device__ __align__(256) __half g_ww1h[2 * ZD * FF];
__device__ __align__(256) __half g_ww2h[2 * FF * FF];
__device__ __align__(256) __half g_bw1h[2 * ZD * FF];
__device__ __align__(256) __half g_bw2h[2 * FF * FF];

#define DI __device__ __forceinline__

DI uint32_t smem_u32(const void* p) {
    uint32_t a;
    asm("{ .reg .u64 t; cvta.to.shared.u64 t, %1; cvt.u32.u64 %0, t; }"
        : "=r"(a) : "l"(p));
    return a;
}
DI void cp16(uint32_t dst, const void* src) {
    asm volatile("cp.async.cg.shared.global [%0], [%1], 16;"
                 :: "r"(dst), "l"(src));
}
DI void cp16z(uint32_t dst, const void* src, int valid) {  // zero-fill if !valid
    asm volatile("cp.async.cg.shared.global [%0], [%1], 16, %2;"
                 :: "r"(dst), "l"(src), "r"(valid ? 16 : 0));
}
DI void cp_commit() { asm volatile("cp.async.commit_group;"); }
DI void cp_wait1()  { asm volatile("cp.async.wait_group 1;"); }

DI void ldsm_x4(uint32_t& r0, uint32_t& r1, uint32_t& r2, uint32_t& r3, uint32_t a) {
    asm volatile("ldmatrix.sync.aligned.m8n8.x4.shared.b16 {%0,%1,%2,%3}, [%4];"
                 : "=r"(r0), "=r"(r1), "=r"(r2), "=r"(r3) : "r"(a));
}
DI void ldsm_x4t(uint32_t& r0, uint32_t& r1, uint32_t& r2, uint32_t& r3, uint32_t a) {
    asm volatile("ldmatrix.sync.aligned.m8n8.x4.trans.shared.b16 {%0,%1,%2,%3}, [%4];"
                 : "=r"(r0), "=r"(r1), "=r"(r2), "=r"(r3) : "r"(a));
}
DI void mma16(float c[4], const uint32_t a[4], uint32_t b0, uint32_t b1) {
    asm volatile(
        "mma.sync.aligned.m16n8k16.row.col.f32.f16.f16.f32 "
        "{%0,%1,%2,%3}, {%4,%5,%6,%7}, {%8,%9}, {%0,%1,%2,%3};"
        : "+f"(c[0]), "+f"(c[1]), "+f"(c[2]), "+f"(c[3])
        : "r"(a[0]), "r"(a[1]), "r"(a[2]), "r"(a[3]), "r"(b0), "r"(b1));
}

// Per-lane ldmatrix base offsets (bytes) within a stage.
// A [m][k] halves, row stride APADH. x4: lanes 0-7 rows m+0..7 @k0,
// 8-15 rows m+8..15 @k0, 16-23 rows m+0..7 @k+8, 24-31 rows m+8..15 @k+8.
DI uint32_t a_lane_base(int lane, int wm) {
    int row = wm + (lane & 7) + ((lane >> 3) & 1) * 8;
    int col = ((lane >> 4) & 1) * 8;
    return (uint32_t)(row * APADH + col) * 2u;
}
// B [k][n] halves, row stride BPADH. x4.trans: lanes 0-7 rows k+0..7 @n0,
// 8-15 rows k+8..15 @n0, 16-23 rows k+0..7 @n+8, 24-31 rows k+8..15 @n+8.
DI uint32_t b_lane_base(int lane, int wn) {
    int row = (lane & 7) + ((lane >> 3) & 1) * 8;
    int col = wn + ((lane >> 4) & 1) * 8;
    return (uint32_t)(row * BPADH + col) * 2u;
}

// Load fragments for one k16 step.
DI void load_frags(uint32_t a_sb, uint32_t b_sb, int ks,
                   uint32_t af[4][4], uint32_t bq[2][4]) {
    const uint32_t ak = a_sb + (uint32_t)(ks * 16) * 2u;
    const uint32_t bk = b_sb + (uint32_t)(ks * 16 * BPADH) * 2u;
#pragma unroll
    for (int mf = 0; mf < 4; mf++)
        ldsm_x4(af[mf][0], af[mf][1], af[mf][2], af[mf][3],
                ak + (uint32_t)(mf * 16 * APADH) * 2u);
#pragma unroll
    for (int nfp = 0; nfp < 2; nfp++)
        ldsm_x4t(bq[nfp][0], bq[nfp][1], bq[nfp][2], bq[nfp][3],
                 bk + (uint32_t)(nfp * 16) * 2u);
}

// One BK=32 chunk: 2 k16 steps, double-buffered fragments.
DI void compute_chunk(uint32_t a_sb, uint32_t b_sb, float acc[4][4][4]) {
    uint32_t af[2][4][4], bq[2][2][4];
    load_frags(a_sb, b_sb, 0, af[0], bq[0]);
#pragma unroll
    for (int ks = 0; ks < 2; ks++) {
        const int cur = ks & 1;
        if (ks < 1) load_frags(a_sb, b_sb, 1, af[1], bq[1]);
#pragma unroll
        for (int mf = 0; mf < 4; mf++)
#pragma unroll
            for (int nf = 0; nf < 4; nf++)
                mma16(acc[mf][nf], af[cur][mf],
                      bq[cur][nf >> 1][(nf & 1) * 2],
                      bq[cur][nf >> 1][(nf & 1) * 2 + 1]);
    }
}

// Elementwise fp32 -> fp16 converter (grid-stride, float4 -> half4).
__global__ void cvt_f16_kernel(const float4* __restrict__ in,
                               uint2* __restrict__ out, int n4) {
    for (int i = blockIdx.x * blockDim.x + threadIdx.x; i < n4;
         i += gridDim.x * blockDim.x) {
        float4 v = in[i];
        __half2 lo = __floats2half2_rn(v.x, v.y);
        __half2 hi = __floats2half2_rn(v.z, v.w);
        uint2 o;
        o.x = *(uint32_t*)&lo; o.y = *(uint32_t*)&hi;
        out[i] = o;
    }
}

// ---------------------------------------------------------------------------
// mma_gemm: C[m, n0:n0+128] = A_row(m)[0:K] @ W[K,512] + biasVec
// A_row(m) = A + b*batchStride + t*rowStride (halves), m = b*rowsPerBatch + t.
// OUTH: write fp16; else fp32.
// ---------------------------------------------------------------------------
template<bool RELU, bool OUTH>
__global__ void __launch_bounds__(256, 2) mma_gemm(
    const __half* __restrict__ A, int rowsPerBatch, int rowStride, long batchStride,
    const __half* __restrict__ W, int K,
    const float* __restrict__ biasVec, void* __restrict__ Cv, int M)
{
    extern __shared__ __half smh[];
    const uint32_t sb = smem_u32(smh);
    const int tid = threadIdx.x, lane = tid & 31, wid = tid >> 5;
    const int m0 = blockIdx.y * BM, n0 = blockIdx.x * BN;

    // A gmem mapping: row am = tid>>1 (0..127), half-chunk ah = (tid&1)*16 halves
    const int am = tid >> 1, ah = (tid & 1) * 16;
    const __half* aptr;
    {
        int mm = m0 + am; if (mm >= M) mm = M - 1;   // clamp; store guarded
        int b = mm / rowsPerBatch, t = mm - b * rowsPerBatch;
        aptr = A + (long)b * batchStride + (long)t * rowStride + ah;
    }
    const uint32_t adst0 = sb + (uint32_t)(am * APADH + ah) * 2u;

    // B gmem mapping: k-row bk = tid>>3 (0..31), n-chunk bn = (tid&7)*16 halves
    const int bk = tid >> 3, bn = (tid & 7) * 16;
    const __half* bptr = W + (long)bk * FF + n0 + bn;
    const uint32_t bdst0 = sb + (uint32_t)(AS_H + bk * BPADH + bn) * 2u;

    const int NC = K / BK;

#define LOAD_STAGE(i)                                                          \
    do {                                                                       \
        const uint32_t off = (uint32_t)(((i) & 1) * STG_H) * 2u;               \
        const __half* asrc = aptr + (i) * BK;                                  \
        cp16(adst0 + off, asrc);                                               \
        cp16(adst0 + off + 16, asrc + 8);                                      \
        const __half* bsrc = bptr + (long)(i) * BK * FF;                       \
        cp16(bdst0 + off, bsrc);                                               \
        cp16(bdst0 + off + 16, bsrc + 8);                                      \
        cp_commit();                                                           \
    } while (0)

    float acc[4][4][4];
#pragma unroll
    for (int a = 0; a < 4; a++)
#pragma unroll
        for (int b = 0; b < 4; b++)
#pragma unroll
            for (int c = 0; c < 4; c++) acc[a][b][c] = 0.f;

    const int wm = (wid & 1) * 64, wn = (wid >> 1) * 32;
    const int g = lane >> 2, t4 = lane & 3;
    const uint32_t abase = a_lane_base(lane, wm);
    const uint32_t bbase = b_lane_base(lane, wn) + (uint32_t)AS_H * 2u;

    LOAD_STAGE(0);

    for (int i = 0; i < NC; i++) {
        if (i + 1 < NC) LOAD_STAGE(i + 1); else cp_commit();
        cp_wait1();                 // stage i complete; stage i+1 in flight
        __syncthreads();
        const uint32_t soff = sb + (uint32_t)((i & 1) * STG_H) * 2u;
        compute_chunk(soff + abase, soff + bbase, acc);
        __syncthreads();            // done with slot (i&1) before reload
    }
#undef LOAD_STAGE

    // epilogue (c frag: m = g(+8), n = t4*2(+1))
    float bv[4][2];
#pragma unroll
    for (int nf = 0; nf < 4; nf++) {
        int nc = n0 + wn + nf * 8 + t4 * 2;
        bv[nf][0] = biasVec[nc]; bv[nf][1] = biasVec[nc + 1];
    }
#pragma unroll
    for (int mf = 0; mf < 4; mf++)
#pragma unroll
        for (int hh = 0; hh < 2; hh++) {
            int m = m0 + wm + mf * 16 + g + hh * 8;
            if (m < M) {
#pragma unroll
                for (int nf = 0; nf < 4; nf++) {
                    float vx = acc[mf][nf][hh * 2 + 0] + bv[nf][0];
                    float vy = acc[mf][nf][hh * 2 + 1] + bv[nf][1];
                    if (RELU) { vx = fmaxf(vx, 0.f); vy = fmaxf(vy, 0.f); }
                    long idx = (long)m * FF + n0 + wn + nf * 8 + t4 * 2;
                    if (OUTH) {
                        __half2 h = __floats2half2_rn(vx, vy);
                        *(__half2*)((__half*)Cv + idx) = h;
                    } else {
                        float2 v; v.x = vx; v.y = vy;
                        *(float2*)((float*)Cv + idx) = v;
                    }
                }
            }
        }
}

// ---------------------------------------------------------------------------
// mma_final: out[b,m,n] = sum_{k=1..4095} x[b,m,k]*wts[b,k-1,n] + biasM[b,m,n]
// A = fp16 x, B row kg reads wts[kg-1]; kg==0 zero-filled.
// grid = (4 n-tiles, 4 m-tiles, 8 batches), K=4096 -> 128 chunks.
// ---------------------------------------------------------------------------
__global__ void __launch_bounds__(256, 2) mma_final(
    const __half* __restrict__ x, const __half* __restrict__ wts,
    const float* __restrict__ biasM, float* __restrict__ out)
{
    extern __shared__ __half smh[];
    const uint32_t sb = smem_u32(smh);
    const int tid = threadIdx.x, lane = tid & 31, wid = tid >> 5;
    const int bz = blockIdx.z;
    const int m0 = blockIdx.y * BM, n0 = blockIdx.x * BN;

    const int am = tid >> 1, ah = (tid & 1) * 16;
    const __half* aptr = x + (long)(bz * 512 + m0 + am) * TT + ah;
    const uint32_t adst0 = sb + (uint32_t)(am * APADH + ah) * 2u;

    const int bk = tid >> 3, bn = (tid & 7) * 16;
    const __half* wb = wts + (long)bz * TT * FF + n0 + bn;
    const uint32_t bdst0 = sb + (uint32_t)(AS_H + bk * BPADH + bn) * 2u;

    const int NC = TT / BK;   // 128

#define LOAD_STAGE_F(i)                                                        \
    do {                                                                       \
        const uint32_t off = (uint32_t)(((i) & 1) * STG_H) * 2u;               \
        const __half* asrc = aptr + (i) * BK;                                  \
        cp16(adst0 + off, asrc);                                               \
        cp16(adst0 + off + 16, asrc + 8);                                      \
        const int kg = (i) * BK + bk;                                          \
        const __half* bsrc = wb + (long)(kg > 0 ? kg - 1 : 0) * FF;            \
        cp16z(bdst0 + off, bsrc, kg > 0);                                      \
        cp16z(bdst0 + off + 16, bsrc + 8, kg > 0);                             \
        cp_commit();                                                           \
    } while (0)

    float acc[4][4][4];
#pragma unroll
    for (int a = 0; a < 4; a++)
#pragma unroll
        for (int b = 0; b < 4; b++)
#pragma unroll
            for (int c = 0; c < 4; c++) acc[a][b][c] = 0.f;

    const int wm = (wid & 1) * 64, wn = (wid >> 1) * 32;
    const int g = lane >> 2, t4 = lane & 3;
    const uint32_t abase = a_lane_base(lane, wm);
    const uint32_t bbase = b_lane_base(lane, wn) + (uint32_t)AS_H * 2u;

    LOAD_STAGE_F(0);

    for (int i = 0; i < NC; i++) {
        if (i + 1 < NC) LOAD_STAGE_F(i + 1); else cp_commit();
        cp_wait1();
        __syncthreads();
        const uint32_t soff = sb + (uint32_t)((i & 1) * STG_H) * 2u;
        compute_chunk(soff + abase, soff + bbase, acc);
        __syncthreads();
    }
#undef LOAD_STAGE_F

    // epilogue: add bias matrix, write fp32 out
#pragma unroll
    for (int mf = 0; mf < 4; mf++)
#pragma unroll
        for (int hh = 0; hh < 2; hh++) {
            int m = m0 + wm + mf * 16 + g + hh * 8;
            const long base = ((long)bz * 512 + m) * FF + n0;
#pragma unroll
            for (int nf = 0; nf < 4; nf++) {
                int nc = wn + nf * 8 + t4 * 2;
                float2 bm = *(const float2*)(biasM + base + nc);
                float2 v;
                v.x = acc[mf][nf][hh * 2 + 0] + bm.x;
                v.y = acc[mf][nf][hh * 2 + 1] + bm.y;
                *(float2*)(out + base + nc) = v;
            }
        }
}

// ---------------------------------------------------------------------------
extern "C" void kernel_launch(void* const* d_in, const int* in_sizes, int n_in,
                              void* d_out, int out_size)
{
    const float* x   = (const float*)d_in[0];
    const float* z   = (const float*)d_in[1];
    const float* ww1 = (const float*)d_in[2];
    const float* wb1 = (const float*)d_in[3];
    const float* ww2 = (const float*)d_in[4];
    const float* wb2 = (const float*)d_in[5];
    const float* bw1 = (const float*)d_in[6];
    const float* bb1 = (const float*)d_in[7];
    const float* bw2 = (const float*)d_in[8];
    const float* bb2 = (const float*)d_in[9];
    float* out = (float*)d_out;

    __half *h1w, *h1b, *wts, *xh, *zh, *ww1h, *ww2h, *bw1h, *bw2h;
    float *bias;
    cudaGetSymbolAddress((void**)&h1w,  g_h1w);
    cudaGetSymbolAddress((void**)&h1b,  g_h1b);
    cudaGetSymbolAddress((void**)&wts,  g_wts);
    cudaGetSymbolAddress((void**)&bias, g_bias);
    cudaGetSymbolAddress((void**)&xh,   g_xh);
    cudaGetSymbolAddress((void**)&zh,   g_zh);
    cudaGetSymbolAddress((void**)&ww1h, g_ww1h);
    cudaGetSymbolAddress((void**)&ww2h, g_ww2h);
    cudaGetSymbolAddress((void**)&bw1h, g_bw1h);
    cudaGetSymbolAddress((void**)&bw2h, g_bw2h);

    cudaFuncSetAttribute(mma_gemm<true, true>,
                         cudaFuncAttributeMaxDynamicSharedMemorySize, SMEM_BYTES);
    cudaFuncSetAttribute(mma_gemm<false, true>,
                         cudaFuncAttributeMaxDynamicSharedMemorySize, SMEM_BYTES);
    cudaFuncSetAttribute(mma_gemm<false, false>,
                         cudaFuncAttributeMaxDynamicSharedMemorySize, SMEM_BYTES);
    cudaFuncSetAttribute(mma_final,
                         cudaFuncAttributeMaxDynamicSharedMemorySize, SMEM_BYTES);

    dim3 thr(256);

    // Pre-convert multiplied operands to fp16.
    auto cvt = [&](const float* in, __half* o, long n) {
        int n4 = (int)(n / 4);
        int grid = (n4 + 255) / 256; if (grid > 8192) grid = 8192;
        cvt_f16_kernel<<<grid, 256>>>((const float4*)in, (uint2*)o, n4);
    };
    cvt(x,   xh,   (long)BATCH * 512 * TT);
    cvt(z,   zh,   (long)BATCH * TZv * ZD);
    cvt(ww1, ww1h, 2 * ZD * FF);
    cvt(ww2, ww2h, 2 * FF * FF);
    cvt(bw1, bw1h, 2 * ZD * FF);
    cvt(bw2, bw2h, 2 * FF * FF);

    // weights conv1 + ReLU: M = 8*4097, K = 256  (out: fp16)
    mma_gemm<true, true><<<dim3(FF / BN, (BATCH * T1W + BM - 1) / BM), thr, SMEM_BYTES>>>(
        zh, T1W, ZD, (long)TZv * ZD, ww1h, 2 * ZD, wb1, h1w, BATCH * T1W);

    // bias conv1 + ReLU (truncated): M = 8*513, K = 256  (out: fp16)
    mma_gemm<true, true><<<dim3(FF / BN, (BATCH * T1B + BM - 1) / BM), thr, SMEM_BYTES>>>(
        zh, T1B, ZD, (long)TZv * ZD, bw1h, 2 * ZD, bb1, h1b, BATCH * T1B);

    // weights conv2: M = 8*4096, K = 1024  (out: fp16, B of final GEMM)
    mma_gemm<false, true><<<dim3(FF / BN, (BATCH * TT) / BM), thr, SMEM_BYTES>>>(
        h1w, TT, FF, (long)T1W * FF, ww2h, 2 * FF, wb2, wts, BATCH * TT);

    // bias conv2 (truncated): M = 8*512, K = 1024  (out: fp32, add-only)
    mma_gemm<false, false><<<dim3(FF / BN, (BATCH * 512) / BM), thr, SMEM_BYTES>>>(
        h1b, 512, FF, (long)T1B * FF, bw2h, 2 * FF, bb2, bias, BATCH * 512);

    // final batched GEMM: per-batch 512x512 @ K=4096(shifted) + bias matrix
    mma_final<<<dim3(FF / BN, 512 / BM, BATCH), thr, SMEM_BYTES>>>(xh, wts, bias, out);
}